// round 8
// baseline (speedup 1.0000x reference)
#include <cuda_runtime.h>
#include <cuda_fp16.h>
#include <cstdint>

#define N_NODES 8192
#define D       512
#define CAP     256

// ---- scratch (device globals) ----
__device__ int    g_csr[N_NODES * CAP];
__device__ int    g_cnt[N_NODES];
__device__ float  g_dis[N_NODES];
__device__ uint2  g_yh[N_NODES * D / 4];   // y = x @ W^T stored as fp16

// =====================================================================
// fp16 mma helper (m16n8k16, f32 accumulate) — legacy mma.sync path;
// tcgen05 is unavailable at this bench's compile target (sm_100 virtual).
// =====================================================================
__device__ __forceinline__ void mma_fp16(float* c, const uint32_t* a, const uint32_t* b) {
    asm volatile(
        "mma.sync.aligned.m16n8k16.row.col.f32.f16.f16.f32 "
        "{%0,%1,%2,%3}, {%4,%5,%6,%7}, {%8,%9}, {%0,%1,%2,%3};\n"
        : "+f"(c[0]), "+f"(c[1]), "+f"(c[2]), "+f"(c[3])
        : "r"(a[0]), "r"(a[1]), "r"(a[2]), "r"(a[3]), "r"(b[0]), "r"(b[1]));
}

// =====================================================================
// Kernel 1: CSR build (one block per row of dense A) — DRAM-bound
// =====================================================================
__global__ __launch_bounds__(256) void build_csr_kernel(const float* __restrict__ A) {
    const int row = blockIdx.x;
    __shared__ int s_cnt;
    if (threadIdx.x == 0) s_cnt = 0;
    __syncthreads();

    const float4* Arow = reinterpret_cast<const float4*>(A + (size_t)row * N_NODES);
    int* csr_row = g_csr + row * CAP;

    for (int v = threadIdx.x; v < N_NODES / 4; v += 256) {
        float4 f = __ldcs(&Arow[v]);
        int base = v * 4;
        if (f.x != 0.0f) { int s = atomicAdd(&s_cnt, 1); if (s < CAP) csr_row[s] = base;     }
        if (f.y != 0.0f) { int s = atomicAdd(&s_cnt, 1); if (s < CAP) csr_row[s] = base + 1; }
        if (f.z != 0.0f) { int s = atomicAdd(&s_cnt, 1); if (s < CAP) csr_row[s] = base + 2; }
        if (f.w != 0.0f) { int s = atomicAdd(&s_cnt, 1); if (s < CAP) csr_row[s] = base + 3; }
    }
    __syncthreads();
    if (threadIdx.x == 0) {
        int c = s_cnt;
        g_cnt[row] = (c < CAP) ? c : CAP;
        g_dis[row] = rsqrtf((float)(c + 1));           // A_tilde = A + I
    }
}

// =====================================================================
// Kernel 2: y = x @ W^T  (fp16 m16n8k16 mma.sync, fragment-major smem,
// double buffered, 24KB smem).  Epilogue stores fp16 y.
// =====================================================================
#define BM 128
#define BN 64
#define BK 32
#define SBUF 3072

__global__ __launch_bounds__(256) void gemm_kernel(const float* __restrict__ x,
                                                   const float* __restrict__ W) {
    __shared__ uint32_t smem[SBUF * 2];               // 24 KB
    const int tid = threadIdx.x;
    const int id = blockIdx.x;
    const int m0 = (id >> 3) * BM;
    const int n0 = (id & 7) * BN;

    const int wid = tid >> 5, lane = tid & 31;
    const int wm = wid & 3;
    const int wn = wid >> 2;
    const int g = lane >> 2, t = lane & 3;

    float acc[2][4][4];
    #pragma unroll
    for (int i = 0; i < 2; i++)
        #pragma unroll
        for (int j = 0; j < 4; j++)
            #pragma unroll
            for (int r = 0; r < 4; r++) acc[i][j][r] = 0.0f;

    float4 pa[4], pb[2];

    auto load_tile = [&](int k0) {
        #pragma unroll
        for (int i = 0; i < 4; i++) {
            int f = tid + i * 256;
            int m = f >> 3, kq = f & 7;
            pa[i] = *reinterpret_cast<const float4*>(&x[(size_t)(m0 + m) * D + k0 + kq * 4]);
        }
        #pragma unroll
        for (int i = 0; i < 2; i++) {
            int f = tid + i * 256;
            int n = f >> 3, kq = f & 7;
            pb[i] = *reinterpret_cast<const float4*>(&W[(size_t)(n0 + n) * D + k0 + kq * 4]);
        }
    };

    auto stage_tile = [&](int buf) {
        uint32_t* sA = smem + buf * SBUF;
        uint32_t* sB = smem + buf * SBUF + 2048;
        #pragma unroll
        for (int i = 0; i < 4; i++) {
            int f = tid + i * 256;
            int m = f >> 3, k0 = (f & 7) * 4;
            const float* p = reinterpret_cast<const float*>(&pa[i]);
            #pragma unroll
            for (int j = 0; j < 2; j++) {
                int k = k0 + 2 * j;
                int ks = k >> 4, mt = m >> 4;
                int ln = (m & 7) * 4 + ((k & 7) >> 1);
                int rg = ((m >> 3) & 1) + (((k >> 3) & 1) << 1);
                __half2 h = __float22half2_rn(make_float2(p[2 * j], p[2 * j + 1]));
                sA[((ks * 8 + mt) * 32 + ln) * 4 + rg] = *reinterpret_cast<uint32_t*>(&h);
            }
        }
        #pragma unroll
        for (int i = 0; i < 2; i++) {
            int f = tid + i * 256;
            int n = f >> 3, k0 = (f & 7) * 4;
            const float* p = reinterpret_cast<const float*>(&pb[i]);
            #pragma unroll
            for (int j = 0; j < 2; j++) {
                int k = k0 + 2 * j;
                int ks = k >> 4, nt = n >> 3;
                int ln = (n & 7) * 4 + ((k & 7) >> 1);
                int rg = (k >> 3) & 1;
                __half2 h = __float22half2_rn(make_float2(p[2 * j], p[2 * j + 1]));
                sB[((ks * 8 + nt) * 32 + ln) * 2 + rg] = *reinterpret_cast<uint32_t*>(&h);
            }
        }
    };

    auto compute = [&](int buf) {
        const uint32_t* sA = smem + buf * SBUF;
        const uint32_t* sB = smem + buf * SBUF + 2048;
        #pragma unroll
        for (int ks = 0; ks < 2; ks++) {
            uint4 afr[2];
            uint2 bfr[4];
            #pragma unroll
            for (int mtl = 0; mtl < 2; mtl++) {
                int slab = ks * 8 + wm * 2 + mtl;
                afr[mtl] = *reinterpret_cast<const uint4*>(&sA[(slab * 32 + lane) * 4]);
            }
            #pragma unroll
            for (int ntl = 0; ntl < 4; ntl++) {
                int slab = ks * 8 + wn * 4 + ntl;
                bfr[ntl] = *reinterpret_cast<const uint2*>(&sB[(slab * 32 + lane) * 2]);
            }
            #pragma unroll
            for (int mtl = 0; mtl < 2; mtl++)
                #pragma unroll
                for (int ntl = 0; ntl < 4; ntl++)
                    mma_fp16(acc[mtl][ntl],
                             reinterpret_cast<const uint32_t*>(&afr[mtl]),
                             reinterpret_cast<const uint32_t*>(&bfr[ntl]));
        }
    };

    load_tile(0);
    stage_tile(0);
    __syncthreads();

    for (int it = 0; it < D / BK; it++) {
        if (it + 1 < D / BK) load_tile((it + 1) * BK);
        compute(it & 1);
        if (it + 1 < D / BK) stage_tile((it + 1) & 1);
        __syncthreads();
    }

    __half* yh = reinterpret_cast<__half*>(g_yh);
    #pragma unroll
    for (int mtl = 0; mtl < 2; mtl++) {
        #pragma unroll
        for (int ntl = 0; ntl < 4; ntl++) {
            const int r0 = m0 + wm * 32 + mtl * 16 + g;
            const int cc = n0 + wn * 32 + ntl * 8 + t * 2;
            __half2 lo = __float22half2_rn(make_float2(acc[mtl][ntl][0], acc[mtl][ntl][1]));
            __half2 hi = __float22half2_rn(make_float2(acc[mtl][ntl][2], acc[mtl][ntl][3]));
            *reinterpret_cast<__half2*>(&yh[(size_t)r0 * D + cc])       = lo;
            *reinterpret_cast<__half2*>(&yh[(size_t)(r0 + 8) * D + cc]) = hi;
        }
    }
}

// =====================================================================
// Kernel 3: aggregate + bias + relu (fp16 gather, fp32 accumulate)
// =====================================================================
__device__ __forceinline__ void acc_edge(float4& acc, float w, uint2 v) {
    float2 a = __half22float2(*reinterpret_cast<__half2*>(&v.x));
    float2 b = __half22float2(*reinterpret_cast<__half2*>(&v.y));
    acc.x += w * a.x; acc.y += w * a.y; acc.z += w * b.x; acc.w += w * b.y;
}

__global__ __launch_bounds__(128) void aggregate_out_kernel(const float* __restrict__ bias,
                                                            float* __restrict__ out,
                                                            int row0) {
    const int row = row0 + blockIdx.x;
    __shared__ int   s_nbr[CAP];
    __shared__ float s_w[CAP];

    const int cnt = g_cnt[row];
    for (int e = threadIdx.x; e < cnt; e += 128) {
        int j = g_csr[row * CAP + e];
        s_nbr[e] = j;
        s_w[e] = g_dis[j];
    }
    __syncthreads();

    const uint2* y4 = g_yh;
    const int c = threadIdx.x;
    const float di = g_dis[row];

    float4 acc = make_float4(0.f, 0.f, 0.f, 0.f);
    acc_edge(acc, di, y4[row * (D / 4) + c]);          // self term

    int e = 0;
    for (; e + 8 <= cnt; e += 8) {
        uint2 v0 = y4[s_nbr[e + 0] * (D / 4) + c];
        uint2 v1 = y4[s_nbr[e + 1] * (D / 4) + c];
        uint2 v2 = y4[s_nbr[e + 2] * (D / 4) + c];
        uint2 v3 = y4[s_nbr[e + 3] * (D / 4) + c];
        uint2 v4 = y4[s_nbr[e + 4] * (D / 4) + c];
        uint2 v5 = y4[s_nbr[e + 5] * (D / 4) + c];
        uint2 v6 = y4[s_nbr[e + 6] * (D / 4) + c];
        uint2 v7 = y4[s_nbr[e + 7] * (D / 4) + c];
        acc_edge(acc, s_w[e + 0], v0);
        acc_edge(acc, s_w[e + 1], v1);
        acc_edge(acc, s_w[e + 2], v2);
        acc_edge(acc, s_w[e + 3], v3);
        acc_edge(acc, s_w[e + 4], v4);
        acc_edge(acc, s_w[e + 5], v5);
        acc_edge(acc, s_w[e + 6], v6);
        acc_edge(acc, s_w[e + 7], v7);
    }
    for (; e < cnt; e++) acc_edge(acc, s_w[e], y4[s_nbr[e] * (D / 4) + c]);

    float4 b4 = reinterpret_cast<const float4*>(bias)[c];
    float4 o;
    o.x = fmaxf(di * acc.x + b4.x, 0.0f);
    o.y = fmaxf(di * acc.y + b4.y, 0.0f);
    o.z = fmaxf(di * acc.z + b4.z, 0.0f);
    o.w = fmaxf(di * acc.w + b4.w, 0.0f);
    reinterpret_cast<float4*>(out)[row * (D / 4) + c] = o;
}

// =====================================================================
extern "C" void kernel_launch(void* const* d_in, const int* in_sizes, int n_in,
                              void* d_out, int out_size) {
    const float *x = nullptr, *A = nullptr, *W = nullptr, *b = nullptr;
    for (int i = 0; i < n_in; i++) {
        switch (in_sizes[i]) {
            case N_NODES * D:              x = (const float*)d_in[i]; break;
            case 67108864 /* 8192^2 */:    A = (const float*)d_in[i]; break;
            case D * D:                    W = (const float*)d_in[i]; break;
            case D:                        b = (const float*)d_in[i]; break;
        }
    }
    float* out = (float*)d_out;

    // Fork csr (DRAM-bound) onto a side stream so it overlaps the
    // tensor-bound gemm on the main stream; join before the aggregate.
    // Fresh handles per call: identical captured work every invocation.
    cudaStream_t side;
    cudaEvent_t ev_fork, ev_join;
    cudaStreamCreateWithFlags(&side, cudaStreamNonBlocking);
    cudaEventCreateWithFlags(&ev_fork, cudaEventDisableTiming);
    cudaEventCreateWithFlags(&ev_join, cudaEventDisableTiming);

    cudaEventRecord(ev_fork, 0);
    cudaStreamWaitEvent(side, ev_fork, 0);

    build_csr_kernel<<<N_NODES, 256, 0, side>>>(A);
    gemm_kernel<<<(N_NODES / BM) * (D / BN), 256>>>(x, W);

    cudaEventRecord(ev_join, side);
    cudaStreamWaitEvent(0, ev_join, 0);

    aggregate_out_kernel<<<N_NODES / 2, 128>>>(b, out, 0);
    aggregate_out_kernel<<<N_NODES / 2, 128>>>(b, out, N_NODES / 2);
}

// round 10
// speedup vs baseline: 1.0625x; 1.0625x over previous
#include <cuda_runtime.h>
#include <cuda_fp16.h>
#include <cstdint>

#define N_NODES 8192
#define D       512
#define CAP     256

// ---- scratch (device globals) ----
__device__ int    g_csr[N_NODES * CAP];
__device__ int    g_cnt[N_NODES];
__device__ float  g_dis[N_NODES];
__device__ uint4  g_ys[N_NODES * D / 8];   // ys = dis[m] * (x @ W^T)[m], fp16 (8 halves/uint4)

// =====================================================================
// fp16 mma helper (m16n8k16, f32 accumulate) — legacy mma.sync path;
// tcgen05 is unavailable at this bench's compile target (sm_100 virtual).
// =====================================================================
__device__ __forceinline__ void mma_fp16(float* c, const uint32_t* a, const uint32_t* b) {
    asm volatile(
        "mma.sync.aligned.m16n8k16.row.col.f32.f16.f16.f32 "
        "{%0,%1,%2,%3}, {%4,%5,%6,%7}, {%8,%9}, {%0,%1,%2,%3};\n"
        : "+f"(c[0]), "+f"(c[1]), "+f"(c[2]), "+f"(c[3])
        : "r"(a[0]), "r"(a[1]), "r"(a[2]), "r"(a[3]), "r"(b[0]), "r"(b[1]));
}

// =====================================================================
// Kernel 1: CSR build (one block per row of dense A) — DRAM-bound
// =====================================================================
__global__ __launch_bounds__(256) void build_csr_kernel(const float* __restrict__ A) {
    const int row = blockIdx.x;
    __shared__ int s_cnt;
    if (threadIdx.x == 0) s_cnt = 0;
    __syncthreads();

    const float4* Arow = reinterpret_cast<const float4*>(A + (size_t)row * N_NODES);
    int* csr_row = g_csr + row * CAP;

    for (int v = threadIdx.x; v < N_NODES / 4; v += 256) {
        float4 f = __ldcs(&Arow[v]);
        int base = v * 4;
        if (f.x != 0.0f) { int s = atomicAdd(&s_cnt, 1); if (s < CAP) csr_row[s] = base;     }
        if (f.y != 0.0f) { int s = atomicAdd(&s_cnt, 1); if (s < CAP) csr_row[s] = base + 1; }
        if (f.z != 0.0f) { int s = atomicAdd(&s_cnt, 1); if (s < CAP) csr_row[s] = base + 2; }
        if (f.w != 0.0f) { int s = atomicAdd(&s_cnt, 1); if (s < CAP) csr_row[s] = base + 3; }
    }
    __syncthreads();
    if (threadIdx.x == 0) {
        int c = s_cnt;
        g_cnt[row] = (c < CAP) ? c : CAP;
        g_dis[row] = rsqrtf((float)(c + 1));           // A_tilde = A + I
    }
}

// =====================================================================
// Kernel 2: ys = dis * (x @ W^T)  (fp16 m16n8k16 mma.sync, fragment-major
// smem, double buffered, 24KB).  dis folded into the epilogue (csr runs
// before gemm), so the aggregate needs no per-edge weights.
// =====================================================================
#define BM 128
#define BN 64
#define BK 32
#define SBUF 3072

__global__ __launch_bounds__(256) void gemm_kernel(const float* __restrict__ x,
                                                   const float* __restrict__ W) {
    __shared__ uint32_t smem[SBUF * 2];               // 24 KB
    const int tid = threadIdx.x;
    const int id = blockIdx.x;
    const int m0 = (id >> 3) * BM;
    const int n0 = (id & 7) * BN;

    const int wid = tid >> 5, lane = tid & 31;
    const int wm = wid & 3;
    const int wn = wid >> 2;
    const int g = lane >> 2, t = lane & 3;

    float acc[2][4][4];
    #pragma unroll
    for (int i = 0; i < 2; i++)
        #pragma unroll
        for (int j = 0; j < 4; j++)
            #pragma unroll
            for (int r = 0; r < 4; r++) acc[i][j][r] = 0.0f;

    float4 pa[4], pb[2];

    auto load_tile = [&](int k0) {
        #pragma unroll
        for (int i = 0; i < 4; i++) {
            int f = tid + i * 256;
            int m = f >> 3, kq = f & 7;
            pa[i] = *reinterpret_cast<const float4*>(&x[(size_t)(m0 + m) * D + k0 + kq * 4]);
        }
        #pragma unroll
        for (int i = 0; i < 2; i++) {
            int f = tid + i * 256;
            int n = f >> 3, kq = f & 7;
            pb[i] = *reinterpret_cast<const float4*>(&W[(size_t)(n0 + n) * D + k0 + kq * 4]);
        }
    };

    auto stage_tile = [&](int buf) {
        uint32_t* sA = smem + buf * SBUF;
        uint32_t* sB = smem + buf * SBUF + 2048;
        #pragma unroll
        for (int i = 0; i < 4; i++) {
            int f = tid + i * 256;
            int m = f >> 3, k0 = (f & 7) * 4;
            const float* p = reinterpret_cast<const float*>(&pa[i]);
            #pragma unroll
            for (int j = 0; j < 2; j++) {
                int k = k0 + 2 * j;
                int ks = k >> 4, mt = m >> 4;
                int ln = (m & 7) * 4 + ((k & 7) >> 1);
                int rg = ((m >> 3) & 1) + (((k >> 3) & 1) << 1);
                __half2 h = __float22half2_rn(make_float2(p[2 * j], p[2 * j + 1]));
                sA[((ks * 8 + mt) * 32 + ln) * 4 + rg] = *reinterpret_cast<uint32_t*>(&h);
            }
        }
        #pragma unroll
        for (int i = 0; i < 2; i++) {
            int f = tid + i * 256;
            int n = f >> 3, k0 = (f & 7) * 4;
            const float* p = reinterpret_cast<const float*>(&pb[i]);
            #pragma unroll
            for (int j = 0; j < 2; j++) {
                int k = k0 + 2 * j;
                int ks = k >> 4, nt = n >> 3;
                int ln = (n & 7) * 4 + ((k & 7) >> 1);
                int rg = (k >> 3) & 1;
                __half2 h = __float22half2_rn(make_float2(p[2 * j], p[2 * j + 1]));
                sB[((ks * 8 + nt) * 32 + ln) * 2 + rg] = *reinterpret_cast<uint32_t*>(&h);
            }
        }
    };

    auto compute = [&](int buf) {
        const uint32_t* sA = smem + buf * SBUF;
        const uint32_t* sB = smem + buf * SBUF + 2048;
        #pragma unroll
        for (int ks = 0; ks < 2; ks++) {
            uint4 afr[2];
            uint2 bfr[4];
            #pragma unroll
            for (int mtl = 0; mtl < 2; mtl++) {
                int slab = ks * 8 + wm * 2 + mtl;
                afr[mtl] = *reinterpret_cast<const uint4*>(&sA[(slab * 32 + lane) * 4]);
            }
            #pragma unroll
            for (int ntl = 0; ntl < 4; ntl++) {
                int slab = ks * 8 + wn * 4 + ntl;
                bfr[ntl] = *reinterpret_cast<const uint2*>(&sB[(slab * 32 + lane) * 2]);
            }
            #pragma unroll
            for (int mtl = 0; mtl < 2; mtl++)
                #pragma unroll
                for (int ntl = 0; ntl < 4; ntl++)
                    mma_fp16(acc[mtl][ntl],
                             reinterpret_cast<const uint32_t*>(&afr[mtl]),
                             reinterpret_cast<const uint32_t*>(&bfr[ntl]));
        }
    };

    load_tile(0);
    stage_tile(0);
    __syncthreads();

    for (int it = 0; it < D / BK; it++) {
        if (it + 1 < D / BK) load_tile((it + 1) * BK);
        compute(it & 1);
        if (it + 1 < D / BK) stage_tile((it + 1) & 1);
        __syncthreads();
    }

    // epilogue: ys = dis[row] * y, stored fp16
    __half* yh = reinterpret_cast<__half*>(g_ys);
    #pragma unroll
    for (int mtl = 0; mtl < 2; mtl++) {
        const int rA = m0 + wm * 32 + mtl * 16 + g;
        const float dA = g_dis[rA];
        const float dB = g_dis[rA + 8];
        #pragma unroll
        for (int ntl = 0; ntl < 4; ntl++) {
            const int cc = n0 + wn * 32 + ntl * 8 + t * 2;
            __half2 lo = __float22half2_rn(
                make_float2(dA * acc[mtl][ntl][0], dA * acc[mtl][ntl][1]));
            __half2 hi = __float22half2_rn(
                make_float2(dB * acc[mtl][ntl][2], dB * acc[mtl][ntl][3]));
            *reinterpret_cast<__half2*>(&yh[(size_t)rA * D + cc])       = lo;
            *reinterpret_cast<__half2*>(&yh[(size_t)(rA + 8) * D + cc]) = hi;
        }
    }
}

// =====================================================================
// Kernel 3: aggregate + bias + relu (unweighted fp16 gather, fp32 acc)
//   out[i,:] = relu( di * ( ys[i,:] + sum_{j in N(i)} ys[j,:] ) + b )
// 64 threads/block, one row/block, uint4 (8 halves) per thread.
// =====================================================================
__device__ __forceinline__ void acc8(float4& a0, float4& a1, uint4 v) {
    float2 p0 = __half22float2(*reinterpret_cast<__half2*>(&v.x));
    float2 p1 = __half22float2(*reinterpret_cast<__half2*>(&v.y));
    float2 p2 = __half22float2(*reinterpret_cast<__half2*>(&v.z));
    float2 p3 = __half22float2(*reinterpret_cast<__half2*>(&v.w));
    a0.x += p0.x; a0.y += p0.y; a0.z += p1.x; a0.w += p1.y;
    a1.x += p2.x; a1.y += p2.y; a1.z += p3.x; a1.w += p3.y;
}

__global__ __launch_bounds__(64) void aggregate_out_kernel(const float* __restrict__ bias,
                                                           float* __restrict__ out) {
    const int row = blockIdx.x;
    __shared__ int s_nbr[CAP];

    const int cnt = g_cnt[row];
    for (int e = threadIdx.x; e < cnt; e += 64) s_nbr[e] = g_csr[row * CAP + e];
    __syncthreads();

    const int c = threadIdx.x;                         // owns cols [8c, 8c+8)
    float4 a0 = make_float4(0.f, 0.f, 0.f, 0.f);
    float4 a1 = make_float4(0.f, 0.f, 0.f, 0.f);
    acc8(a0, a1, g_ys[row * (D / 8) + c]);             // self term (= ys_i)

    int e = 0;
    for (; e + 4 <= cnt; e += 4) {
        uint4 v0 = g_ys[s_nbr[e + 0] * (D / 8) + c];
        uint4 v1 = g_ys[s_nbr[e + 1] * (D / 8) + c];
        uint4 v2 = g_ys[s_nbr[e + 2] * (D / 8) + c];
        uint4 v3 = g_ys[s_nbr[e + 3] * (D / 8) + c];
        acc8(a0, a1, v0);
        acc8(a0, a1, v1);
        acc8(a0, a1, v2);
        acc8(a0, a1, v3);
    }
    for (; e < cnt; e++) acc8(a0, a1, g_ys[s_nbr[e] * (D / 8) + c]);

    const float di = g_dis[row];
    const float4 b0 = reinterpret_cast<const float4*>(bias)[2 * c];
    const float4 b1 = reinterpret_cast<const float4*>(bias)[2 * c + 1];
    float4 o0, o1;
    o0.x = fmaxf(di * a0.x + b0.x, 0.0f);
    o0.y = fmaxf(di * a0.y + b0.y, 0.0f);
    o0.z = fmaxf(di * a0.z + b0.z, 0.0f);
    o0.w = fmaxf(di * a0.w + b0.w, 0.0f);
    o1.x = fmaxf(di * a1.x + b1.x, 0.0f);
    o1.y = fmaxf(di * a1.y + b1.y, 0.0f);
    o1.z = fmaxf(di * a1.z + b1.z, 0.0f);
    o1.w = fmaxf(di * a1.w + b1.w, 0.0f);
    reinterpret_cast<float4*>(out)[row * (D / 4) + 2 * c]     = o0;
    reinterpret_cast<float4*>(out)[row * (D / 4) + 2 * c + 1] = o1;
}

// =====================================================================
extern "C" void kernel_launch(void* const* d_in, const int* in_sizes, int n_in,
                              void* d_out, int out_size) {
    const float *x = nullptr, *A = nullptr, *W = nullptr, *b = nullptr;
    for (int i = 0; i < n_in; i++) {
        switch (in_sizes[i]) {
            case N_NODES * D:              x = (const float*)d_in[i]; break;
            case 67108864 /* 8192^2 */:    A = (const float*)d_in[i]; break;
            case D * D:                    W = (const float*)d_in[i]; break;
            case D:                        b = (const float*)d_in[i]; break;
        }
    }
    float* out = (float*)d_out;

    // Serial launches on the capture stream. Stream-fork overlap measured
    // as a zero-gain (R8: 114.7 vs 114.9 serial) and leaked handles; dropped.
    build_csr_kernel<<<N_NODES, 256>>>(A);             // writes g_cnt, g_dis
    gemm_kernel<<<(N_NODES / BM) * (D / BN), 256>>>(x, W);  // reads g_dis (epilogue)
    aggregate_out_kernel<<<N_NODES, 64>>>(b, out);
}

// round 11
// speedup vs baseline: 1.1044x; 1.0395x over previous
#include <cuda_runtime.h>
#include <cuda_fp16.h>
#include <cstdint>

#define N_NODES 8192
#define D       512
#define CAP     256

// ---- scratch (device globals) ----
__device__ int    g_csr[N_NODES * CAP];
__device__ int    g_cnt[N_NODES];
__device__ float  g_dis[N_NODES];
__device__ uint4  g_ys[N_NODES * D / 8];   // ys = dis[m] * (x @ W^T)[m], fp16 (8 halves/uint4)

// =====================================================================
// fp16 mma helper (m16n8k16, f32 accumulate) — legacy mma.sync path;
// tcgen05 is unavailable at this bench's compile target (sm_100 virtual).
// =====================================================================
__device__ __forceinline__ void mma_fp16(float* c, const uint32_t* a, const uint32_t* b) {
    asm volatile(
        "mma.sync.aligned.m16n8k16.row.col.f32.f16.f16.f32 "
        "{%0,%1,%2,%3}, {%4,%5,%6,%7}, {%8,%9}, {%0,%1,%2,%3};\n"
        : "+f"(c[0]), "+f"(c[1]), "+f"(c[2]), "+f"(c[3])
        : "r"(a[0]), "r"(a[1]), "r"(a[2]), "r"(a[3]), "r"(b[0]), "r"(b[1]));
}

// =====================================================================
// Kernel 1: CSR build — one block per row of dense A.
// Loads are PREFETCHED into registers first (8 independent LDG.128 per
// thread, MLP=8) so the conditional-compaction scan doesn't serialize
// the DRAM stream.  (R10 profile: DRAM 66.5% with in-loop loads.)
// =====================================================================
__global__ __launch_bounds__(256) void build_csr_kernel(const float* __restrict__ A) {
    const int row = blockIdx.x;
    __shared__ int s_cnt;
    if (threadIdx.x == 0) s_cnt = 0;
    __syncthreads();

    const float4* Arow = reinterpret_cast<const float4*>(A + (size_t)row * N_NODES);
    int* csr_row = g_csr + row * CAP;

    // batched front loads: 8 x LDG.128, no dependent work between them
    float4 f[8];
    #pragma unroll
    for (int i = 0; i < 8; i++)
        f[i] = __ldcs(&Arow[threadIdx.x + i * 256]);

    // compaction scan on registers
    #pragma unroll
    for (int i = 0; i < 8; i++) {
        int base = (threadIdx.x + i * 256) * 4;
        if (f[i].x != 0.0f) { int s = atomicAdd(&s_cnt, 1); if (s < CAP) csr_row[s] = base;     }
        if (f[i].y != 0.0f) { int s = atomicAdd(&s_cnt, 1); if (s < CAP) csr_row[s] = base + 1; }
        if (f[i].z != 0.0f) { int s = atomicAdd(&s_cnt, 1); if (s < CAP) csr_row[s] = base + 2; }
        if (f[i].w != 0.0f) { int s = atomicAdd(&s_cnt, 1); if (s < CAP) csr_row[s] = base + 3; }
    }
    __syncthreads();
    if (threadIdx.x == 0) {
        int c = s_cnt;
        g_cnt[row] = (c < CAP) ? c : CAP;
        g_dis[row] = rsqrtf((float)(c + 1));           // A_tilde = A + I
    }
}

// =====================================================================
// Kernel 2: ys = dis * (x @ W^T)  (fp16 m16n8k16 mma.sync, fragment-major
// smem, double buffered, 24KB).  dis folded into the epilogue.
// =====================================================================
#define BM 128
#define BN 64
#define BK 32
#define SBUF 3072

__global__ __launch_bounds__(256) void gemm_kernel(const float* __restrict__ x,
                                                   const float* __restrict__ W) {
    __shared__ uint32_t smem[SBUF * 2];               // 24 KB
    const int tid = threadIdx.x;
    const int id = blockIdx.x;
    const int m0 = (id >> 3) * BM;
    const int n0 = (id & 7) * BN;

    const int wid = tid >> 5, lane = tid & 31;
    const int wm = wid & 3;
    const int wn = wid >> 2;
    const int g = lane >> 2, t = lane & 3;

    float acc[2][4][4];
    #pragma unroll
    for (int i = 0; i < 2; i++)
        #pragma unroll
        for (int j = 0; j < 4; j++)
            #pragma unroll
            for (int r = 0; r < 4; r++) acc[i][j][r] = 0.0f;

    float4 pa[4], pb[2];

    auto load_tile = [&](int k0) {
        #pragma unroll
        for (int i = 0; i < 4; i++) {
            int f = tid + i * 256;
            int m = f >> 3, kq = f & 7;
            pa[i] = *reinterpret_cast<const float4*>(&x[(size_t)(m0 + m) * D + k0 + kq * 4]);
        }
        #pragma unroll
        for (int i = 0; i < 2; i++) {
            int f = tid + i * 256;
            int n = f >> 3, kq = f & 7;
            pb[i] = *reinterpret_cast<const float4*>(&W[(size_t)(n0 + n) * D + k0 + kq * 4]);
        }
    };

    auto stage_tile = [&](int buf) {
        uint32_t* sA = smem + buf * SBUF;
        uint32_t* sB = smem + buf * SBUF + 2048;
        #pragma unroll
        for (int i = 0; i < 4; i++) {
            int f = tid + i * 256;
            int m = f >> 3, k0 = (f & 7) * 4;
            const float* p = reinterpret_cast<const float*>(&pa[i]);
            #pragma unroll
            for (int j = 0; j < 2; j++) {
                int k = k0 + 2 * j;
                int ks = k >> 4, mt = m >> 4;
                int ln = (m & 7) * 4 + ((k & 7) >> 1);
                int rg = ((m >> 3) & 1) + (((k >> 3) & 1) << 1);
                __half2 h = __float22half2_rn(make_float2(p[2 * j], p[2 * j + 1]));
                sA[((ks * 8 + mt) * 32 + ln) * 4 + rg] = *reinterpret_cast<uint32_t*>(&h);
            }
        }
        #pragma unroll
        for (int i = 0; i < 2; i++) {
            int f = tid + i * 256;
            int n = f >> 3, k0 = (f & 7) * 4;
            const float* p = reinterpret_cast<const float*>(&pb[i]);
            #pragma unroll
            for (int j = 0; j < 2; j++) {
                int k = k0 + 2 * j;
                int ks = k >> 4, nt = n >> 3;
                int ln = (n & 7) * 4 + ((k & 7) >> 1);
                int rg = (k >> 3) & 1;
                __half2 h = __float22half2_rn(make_float2(p[2 * j], p[2 * j + 1]));
                sB[((ks * 8 + nt) * 32 + ln) * 2 + rg] = *reinterpret_cast<uint32_t*>(&h);
            }
        }
    };

    auto compute = [&](int buf) {
        const uint32_t* sA = smem + buf * SBUF;
        const uint32_t* sB = smem + buf * SBUF + 2048;
        #pragma unroll
        for (int ks = 0; ks < 2; ks++) {
            uint4 afr[2];
            uint2 bfr[4];
            #pragma unroll
            for (int mtl = 0; mtl < 2; mtl++) {
                int slab = ks * 8 + wm * 2 + mtl;
                afr[mtl] = *reinterpret_cast<const uint4*>(&sA[(slab * 32 + lane) * 4]);
            }
            #pragma unroll
            for (int ntl = 0; ntl < 4; ntl++) {
                int slab = ks * 8 + wn * 4 + ntl;
                bfr[ntl] = *reinterpret_cast<const uint2*>(&sB[(slab * 32 + lane) * 2]);
            }
            #pragma unroll
            for (int mtl = 0; mtl < 2; mtl++)
                #pragma unroll
                for (int ntl = 0; ntl < 4; ntl++)
                    mma_fp16(acc[mtl][ntl],
                             reinterpret_cast<const uint32_t*>(&afr[mtl]),
                             reinterpret_cast<const uint32_t*>(&bfr[ntl]));
        }
    };

    load_tile(0);
    stage_tile(0);
    __syncthreads();

    for (int it = 0; it < D / BK; it++) {
        if (it + 1 < D / BK) load_tile((it + 1) * BK);
        compute(it & 1);
        if (it + 1 < D / BK) stage_tile((it + 1) & 1);
        __syncthreads();
    }

    // epilogue: ys = dis[row] * y, stored fp16
    __half* yh = reinterpret_cast<__half*>(g_ys);
    #pragma unroll
    for (int mtl = 0; mtl < 2; mtl++) {
        const int rA = m0 + wm * 32 + mtl * 16 + g;
        const float dA = g_dis[rA];
        const float dB = g_dis[rA + 8];
        #pragma unroll
        for (int ntl = 0; ntl < 4; ntl++) {
            const int cc = n0 + wn * 32 + ntl * 8 + t * 2;
            __half2 lo = __float22half2_rn(
                make_float2(dA * acc[mtl][ntl][0], dA * acc[mtl][ntl][1]));
            __half2 hi = __float22half2_rn(
                make_float2(dB * acc[mtl][ntl][2], dB * acc[mtl][ntl][3]));
            *reinterpret_cast<__half2*>(&yh[(size_t)rA * D + cc])       = lo;
            *reinterpret_cast<__half2*>(&yh[(size_t)(rA + 8) * D + cc]) = hi;
        }
    }
}

// =====================================================================
// Kernel 3: aggregate + bias + relu (unweighted fp16 gather, fp32 acc)
//   out[i,:] = relu( di * ( ys[i,:] + sum_{j in N(i)} ys[j,:] ) + b )
// =====================================================================
__device__ __forceinline__ void acc8(float4& a0, float4& a1, uint4 v) {
    float2 p0 = __half22float2(*reinterpret_cast<__half2*>(&v.x));
    float2 p1 = __half22float2(*reinterpret_cast<__half2*>(&v.y));
    float2 p2 = __half22float2(*reinterpret_cast<__half2*>(&v.z));
    float2 p3 = __half22float2(*reinterpret_cast<__half2*>(&v.w));
    a0.x += p0.x; a0.y += p0.y; a0.z += p1.x; a0.w += p1.y;
    a1.x += p2.x; a1.y += p2.y; a1.z += p3.x; a1.w += p3.y;
}

__global__ __launch_bounds__(64) void aggregate_out_kernel(const float* __restrict__ bias,
                                                           float* __restrict__ out) {
    const int row = blockIdx.x;
    __shared__ int s_nbr[CAP];

    const int cnt = g_cnt[row];
    for (int e = threadIdx.x; e < cnt; e += 64) s_nbr[e] = g_csr[row * CAP + e];
    __syncthreads();

    const int c = threadIdx.x;                         // owns cols [8c, 8c+8)
    float4 a0 = make_float4(0.f, 0.f, 0.f, 0.f);
    float4 a1 = make_float4(0.f, 0.f, 0.f, 0.f);
    acc8(a0, a1, g_ys[row * (D / 8) + c]);             // self term (= ys_i)

    int e = 0;
    for (; e + 4 <= cnt; e += 4) {
        uint4 v0 = g_ys[s_nbr[e + 0] * (D / 8) + c];
        uint4 v1 = g_ys[s_nbr[e + 1] * (D / 8) + c];
        uint4 v2 = g_ys[s_nbr[e + 2] * (D / 8) + c];
        uint4 v3 = g_ys[s_nbr[e + 3] * (D / 8) + c];
        acc8(a0, a1, v0);
        acc8(a0, a1, v1);
        acc8(a0, a1, v2);
        acc8(a0, a1, v3);
    }
    for (; e < cnt; e++) acc8(a0, a1, g_ys[s_nbr[e] * (D / 8) + c]);

    const float di = g_dis[row];
    const float4 b0 = reinterpret_cast<const float4*>(bias)[2 * c];
    const float4 b1 = reinterpret_cast<const float4*>(bias)[2 * c + 1];
    float4 o0, o1;
    o0.x = fmaxf(di * a0.x + b0.x, 0.0f);
    o0.y = fmaxf(di * a0.y + b0.y, 0.0f);
    o0.z = fmaxf(di * a0.z + b0.z, 0.0f);
    o0.w = fmaxf(di * a0.w + b0.w, 0.0f);
    o1.x = fmaxf(di * a1.x + b1.x, 0.0f);
    o1.y = fmaxf(di * a1.y + b1.y, 0.0f);
    o1.z = fmaxf(di * a1.z + b1.z, 0.0f);
    o1.w = fmaxf(di * a1.w + b1.w, 0.0f);
    reinterpret_cast<float4*>(out)[row * (D / 4) + 2 * c]     = o0;
    reinterpret_cast<float4*>(out)[row * (D / 4) + 2 * c + 1] = o1;
}

// =====================================================================
extern "C" void kernel_launch(void* const* d_in, const int* in_sizes, int n_in,
                              void* d_out, int out_size) {
    const float *x = nullptr, *A = nullptr, *W = nullptr, *b = nullptr;
    for (int i = 0; i < n_in; i++) {
        switch (in_sizes[i]) {
            case N_NODES * D:              x = (const float*)d_in[i]; break;
            case 67108864 /* 8192^2 */:    A = (const float*)d_in[i]; break;
            case D * D:                    W = (const float*)d_in[i]; break;
            case D:                        b = (const float*)d_in[i]; break;
        }
    }
    float* out = (float*)d_out;

    build_csr_kernel<<<N_NODES, 256>>>(A);             // writes g_cnt, g_dis
    gemm_kernel<<<(N_NODES / BM) * (D / BN), 256>>>(x, W);  // reads g_dis (epilogue)
    aggregate_out_kernel<<<N_NODES, 64>>>(b, out);
}